// round 1
// baseline (speedup 1.0000x reference)
#include <cuda_runtime.h>
#include <cstdint>

// NeRF volume-rendering integrator.
// raw:    (N, S=128, 4) f32   -> chs = raw[...,0:3], sigma = raw[...,3]
// zvals:  (N, 128) f32 (sorted ascending)
// rays_d: (N, 3) f32
// out:    [chs_map (N*3) | depth_map (N) | sparsity_loss (1)]  f32
//
// One warp per ray. Lane l handles samples s = 32k + l, k = 0..3.
// Transmittance cumprod via warp inclusive-scan product per 32-sample chunk
// combined with a running prefix carried across chunks.
// sum(probs) == 1 + 1e-6 analytically, so entropy normalization is constant.
// Global sparsity loss accumulated into a __device__ double via atomicAdd
// (zeroed by a prologue kernel, emitted by an epilogue kernel).

#define NEAR_F     2.0f
#define FAR_F      6.0f
#define FARDIST_F  1e10f
#define FLT_MIN_CLIP (-3.4028234663852886e38f)

__device__ double g_ent_accum;

__global__ void zero_accum_kernel() {
    g_ent_accum = 0.0;
}

__global__ __launch_bounds__(256) void integrate_kernel(
    const float* __restrict__ raw,
    const float* __restrict__ zvals,
    const float* __restrict__ rays_d,
    float* __restrict__ out,
    int N)
{
    const unsigned FULL = 0xffffffffu;
    int gwarp = (int)((blockIdx.x * blockDim.x + threadIdx.x) >> 5);
    int lane  = (int)(threadIdx.x & 31);
    if (gwarp >= N) return;

    const float4* __restrict__ raw_r = (const float4*)(raw + (size_t)gwarp * 512);
    const float*  __restrict__ z_r   = zvals + (size_t)gwarp * 128;

    // |rays_d| — uniform address across the warp, single broadcast L1 access.
    float dx = rays_d[gwarp * 3 + 0];
    float dy = rays_d[gwarp * 3 + 1];
    float dz = rays_d[gwarp * 3 + 2];
    float nrm = sqrtf(dx * dx + dy * dy + dz * dz);

    const float invDen = 1.0f / (1.0f + 1e-6f);   // 1 / sum(probs)
    const float invFN  = 1.0f / (FAR_F - NEAR_F);

    float running = 1.0f;   // transmittance entering current chunk
    float c0 = 0.f, c1 = 0.f, c2 = 0.f;
    float wsum = 0.f, wz = 0.f, ent = 0.f;

    #pragma unroll
    for (int k = 0; k < 4; ++k) {
        int s = k * 32 + lane;

        float4 rv = raw_r[s];          // coalesced 512B per warp
        float  z  = z_r[s];            // coalesced 128B per warp

        // dist_s = z[s+1] - z[s]  (FAR_DIST for s==127), scaled by |rays_d|
        float znext = __shfl_down_sync(FULL, z, 1);
        if (lane == 31 && s < 127) znext = z_r[s + 1];
        float dist = (s == 127) ? (FARDIST_F * nrm) : ((znext - z) * nrm);

        float sigma = fmaxf(rv.w, 0.0f);
        float e     = expf(-sigma * dist);
        float alpha = 1.0f - e;
        float t     = e + 1e-10f;      // 1 - alpha + 1e-10

        // warp inclusive scan (product) of t
        float incl = t;
        #pragma unroll
        for (int off = 1; off < 32; off <<= 1) {
            float v = __shfl_up_sync(FULL, incl, off);
            if (lane >= off) incl *= v;
        }
        float excl = __shfl_up_sync(FULL, incl, 1);
        if (lane == 0) excl = 1.0f;

        float trans = running * excl;
        float w = alpha * trans;

        c0   += w * rv.x;
        c1   += w * rv.y;
        c2   += w * rv.z;
        wsum += w;
        wz   += w * (FAR_F - z) * invFN;

        // entropy contribution: p = w / (1+1e-6); clip log to f32 finfo.min
        float p  = w * invDen;
        float lp = fmaxf(logf(p), FLT_MIN_CLIP);
        ent -= p * lp;

        running *= __shfl_sync(FULL, incl, 31);
    }

    // warp tree-reduce the 6 accumulators
    #pragma unroll
    for (int off = 16; off > 0; off >>= 1) {
        c0   += __shfl_down_sync(FULL, c0,   off);
        c1   += __shfl_down_sync(FULL, c1,   off);
        c2   += __shfl_down_sync(FULL, c2,   off);
        wsum += __shfl_down_sync(FULL, wsum, off);
        wz   += __shfl_down_sync(FULL, wz,   off);
        ent  += __shfl_down_sync(FULL, ent,  off);
    }

    if (lane == 0) {
        // final prob bucket: (1 - sum(w) + 1e-6) / (1 + 1e-6)
        float pl  = (1.0f - wsum + 1e-6f) * invDen;
        float lpl = fmaxf(logf(pl), FLT_MIN_CLIP);
        ent -= pl * lpl;

        out[(size_t)gwarp * 3 + 0] = c0;
        out[(size_t)gwarp * 3 + 1] = c1;
        out[(size_t)gwarp * 3 + 2] = c2;
        out[(size_t)3 * N + gwarp] = wz / (wsum + 1e-5f);

        atomicAdd(&g_ent_accum, (double)ent);
    }
}

__global__ void finalize_kernel(float* __restrict__ out, int N) {
    out[(size_t)4 * N] = (float)g_ent_accum;
}

extern "C" void kernel_launch(void* const* d_in, const int* in_sizes, int n_in,
                              void* d_out, int out_size)
{
    const float* raw    = (const float*)d_in[0];
    const float* zvals  = (const float*)d_in[1];
    const float* rays_d = (const float*)d_in[2];
    float* out = (float*)d_out;

    int N = in_sizes[0] / 512;   // (N, 128, 4)

    zero_accum_kernel<<<1, 1>>>();

    // one warp per ray; 256 threads = 8 rays per block
    int raysPerBlock = 8;
    int grid = (N + raysPerBlock - 1) / raysPerBlock;
    integrate_kernel<<<grid, 256>>>(raw, zvals, rays_d, out, N);

    finalize_kernel<<<1, 1>>>(out, N);
}

// round 3
// speedup vs baseline: 2.5000x; 2.5000x over previous
#include <cuda_runtime.h>
#include <cstdint>

// NeRF volume-rendering integrator — round 3.
// R1: 112.6us, bottleneck = 65536 single-address atomicAdd(double) at L2 (~serialized).
// R2 fix (this round, redux.f32 reverted to shfl tree — unsupported at this target):
//   per-block smem entropy reduction -> ONE global atomic per block (8192 total).
//
// raw:    (N, S=128, 4) f32   -> chs = raw[...,0:3], sigma = raw[...,3]
// zvals:  (N, 128) f32 (sorted ascending)
// rays_d: (N, 3) f32
// out:    [chs_map (N*3) | depth_map (N) | sparsity_loss (1)]  f32

#define NEAR_F     2.0f
#define FAR_F      6.0f
#define FARDIST_F  1e10f
#define FLT_MIN_CLIP (-3.4028234663852886e38f)

__device__ double g_ent_accum;

__global__ void zero_accum_kernel() {
    g_ent_accum = 0.0;
}

__global__ __launch_bounds__(256) void integrate_kernel(
    const float* __restrict__ raw,
    const float* __restrict__ zvals,
    const float* __restrict__ rays_d,
    float* __restrict__ out,
    int N)
{
    const unsigned FULL = 0xffffffffu;
    __shared__ double s_ent;

    if (threadIdx.x == 0) s_ent = 0.0;
    __syncthreads();

    int gwarp = (int)((blockIdx.x * blockDim.x + threadIdx.x) >> 5);
    int lane  = (int)(threadIdx.x & 31);

    if (gwarp < N) {
        const float4* __restrict__ raw_r = (const float4*)(raw + (size_t)gwarp * 512);
        const float*  __restrict__ z_r   = zvals + (size_t)gwarp * 128;

        // |rays_d| — uniform address across the warp, single broadcast access.
        float dx = rays_d[gwarp * 3 + 0];
        float dy = rays_d[gwarp * 3 + 1];
        float dz = rays_d[gwarp * 3 + 2];
        float nrm = sqrtf(dx * dx + dy * dy + dz * dz);

        const float invDen = 1.0f / (1.0f + 1e-6f);   // 1 / sum(probs)
        const float invFN  = 1.0f / (FAR_F - NEAR_F);

        float running = 1.0f;   // transmittance entering current chunk
        float c0 = 0.f, c1 = 0.f, c2 = 0.f;
        float wsum = 0.f, wz = 0.f, ent = 0.f;

        #pragma unroll
        for (int k = 0; k < 4; ++k) {
            int s = k * 32 + lane;

            float4 rv = raw_r[s];          // coalesced 512B per warp
            float  z  = z_r[s];            // coalesced 128B per warp

            // dist_s = z[s+1] - z[s]  (FAR_DIST for s==127), scaled by |rays_d|
            float znext = __shfl_down_sync(FULL, z, 1);
            if (lane == 31 && s < 127) znext = z_r[s + 1];
            float dist = (s == 127) ? (FARDIST_F * nrm) : ((znext - z) * nrm);

            float sigma = fmaxf(rv.w, 0.0f);
            float e     = expf(-sigma * dist);
            float alpha = 1.0f - e;
            float t     = e + 1e-10f;      // 1 - alpha + 1e-10

            // warp inclusive scan (product) of t
            float incl = t;
            #pragma unroll
            for (int off = 1; off < 32; off <<= 1) {
                float v = __shfl_up_sync(FULL, incl, off);
                if (lane >= off) incl *= v;
            }
            float excl = __shfl_up_sync(FULL, incl, 1);
            if (lane == 0) excl = 1.0f;

            float trans = running * excl;
            float w = alpha * trans;

            c0   += w * rv.x;
            c1   += w * rv.y;
            c2   += w * rv.z;
            wsum += w;
            wz   += w * (FAR_F - z) * invFN;

            // entropy contribution: p = w / (1+1e-6); clip log to f32 finfo.min
            float p  = w * invDen;
            float lp = fmaxf(logf(p), FLT_MIN_CLIP);
            ent -= p * lp;

            running *= __shfl_sync(FULL, incl, 31);
        }

        // warp tree-reduce the 6 accumulators
        #pragma unroll
        for (int off = 16; off > 0; off >>= 1) {
            c0   += __shfl_down_sync(FULL, c0,   off);
            c1   += __shfl_down_sync(FULL, c1,   off);
            c2   += __shfl_down_sync(FULL, c2,   off);
            wsum += __shfl_down_sync(FULL, wsum, off);
            wz   += __shfl_down_sync(FULL, wz,   off);
            ent  += __shfl_down_sync(FULL, ent,  off);
        }

        if (lane == 0) {
            // final prob bucket: (1 - sum(w) + 1e-6) / (1 + 1e-6)
            float pl  = (1.0f - wsum + 1e-6f) * invDen;
            float lpl = fmaxf(logf(pl), FLT_MIN_CLIP);
            ent -= pl * lpl;

            out[(size_t)gwarp * 3 + 0] = c0;
            out[(size_t)gwarp * 3 + 1] = c1;
            out[(size_t)gwarp * 3 + 2] = c2;
            out[(size_t)3 * N + gwarp] = wz / (wsum + 1e-5f);

            // per-block accumulation in shared memory (8 adds/block)
            atomicAdd(&s_ent, (double)ent);
        }
    }

    __syncthreads();
    if (threadIdx.x == 0) {
        // ONE global atomic per block -> 8192 single-address atomics total
        atomicAdd(&g_ent_accum, s_ent);
    }
}

__global__ void finalize_kernel(float* __restrict__ out, int N) {
    out[(size_t)4 * N] = (float)g_ent_accum;
}

extern "C" void kernel_launch(void* const* d_in, const int* in_sizes, int n_in,
                              void* d_out, int out_size)
{
    const float* raw    = (const float*)d_in[0];
    const float* zvals  = (const float*)d_in[1];
    const float* rays_d = (const float*)d_in[2];
    float* out = (float*)d_out;

    int N = in_sizes[0] / 512;   // (N, 128, 4)

    zero_accum_kernel<<<1, 1>>>();

    // one warp per ray; 256 threads = 8 rays per block
    int raysPerBlock = 8;
    int grid = (N + raysPerBlock - 1) / raysPerBlock;
    integrate_kernel<<<grid, 256>>>(raw, zvals, rays_d, out, N);

    finalize_kernel<<<1, 1>>>(out, N);
}